// round 1
// baseline (speedup 1.0000x reference)
#include <cuda_runtime.h>

// Problem constants (fixed shapes from reference)
#define HW    16384      // H*W = 128*128
#define ROWS  4096       // B*C = 32*128
#define CC    128        // channels
#define BB    32         // batch
#define TOPK  1638       // round(16384 * 0.1)
#define HID   8          // C // 16
#define NT    512        // threads per top-k block
#define SMEM_BYTES ((HW + 3*256 + 8) * 4)

__device__ float g_avg[ROWS];
__device__ float g_maxv[ROWS];
__device__ float g_scale[ROWS];

// Order-preserving float->uint key (larger float => larger key)
__device__ __forceinline__ unsigned f2key(float f) {
    unsigned u = __float_as_uint(f);
    return (u & 0x80000000u) ? ~u : (u | 0x80000000u);
}
__device__ __forceinline__ float key2f(unsigned k) {
    unsigned u = (k & 0x80000000u) ? (k ^ 0x80000000u) : ~k;
    return __uint_as_float(u);
}

// Warp-aggregated histogram add (d == -1 means "skip")
__device__ __forceinline__ void agg_add(int* hist, int d) {
    unsigned m = __match_any_sync(0xffffffffu, d);
    int leader = __ffs((int)m) - 1;
    if ((int)(threadIdx.x & 31) == leader && d >= 0)
        atomicAdd(&hist[d], __popc(m));
}

// ---------------------------------------------------------------------------
// Pass 1: per-(b,c) exact top-k mean + max via 4-level radix select in SMEM
// ---------------------------------------------------------------------------
__global__ __launch_bounds__(NT) void topk_stats(const float* __restrict__ x) {
    extern __shared__ unsigned sm[];
    unsigned* keys = sm;                       // HW keys
    int* hist = (int*)(sm + HW);               // 256
    int* sa   = hist + 256;                    // 256 (scan ping)
    int* sb   = sa + 256;                      // 256 (scan pong)
    unsigned* bc = (unsigned*)(sb + 256);      // broadcast: [0]=prefix [1]=remaining

    const int tid = threadIdx.x;
    const int row = blockIdx.x;
    const float4* xin = (const float4*)(x + (size_t)row * HW);
    uint4* kv = (uint4*)keys;

    if (tid < 256) hist[tid] = 0;
    __syncthreads();

    // Load row, build keys, level-0 (top byte) histogram, track max
    unsigned lmax = 0;
#pragma unroll
    for (int i = 0; i < HW / (4 * NT); i++) {
        int idx = tid + i * NT;                // float4 index
        float4 v = xin[idx];
        unsigned k0 = f2key(v.x), k1 = f2key(v.y), k2 = f2key(v.z), k3 = f2key(v.w);
        kv[idx] = make_uint4(k0, k1, k2, k3);
        lmax = max(lmax, max(max(k0, k1), max(k2, k3)));
        agg_add(hist, (int)(k0 >> 24));
        agg_add(hist, (int)(k1 >> 24));
        agg_add(hist, (int)(k2 >> 24));
        agg_add(hist, (int)(k3 >> 24));
    }
#pragma unroll
    for (int o = 16; o; o >>= 1)
        lmax = max(lmax, __shfl_down_sync(0xffffffffu, lmax, o));
    __syncthreads();
    if ((tid & 31) == 0) ((unsigned*)sa)[tid >> 5] = lmax;
    if (tid == 0) { bc[0] = 0u; bc[1] = (unsigned)TOPK; }
    __syncthreads();
    if (tid == 0) {
        unsigned m = 0;
        for (int w = 0; w < NT / 32; w++) m = max(m, ((unsigned*)sa)[w]);
        g_maxv[row] = key2f(m);
    }
    __syncthreads();

    // 4 radix levels, 8 bits each (MSB first). Level 0 hist already built.
    for (int lvl = 0; lvl < 4; lvl++) {
        const int shift = 24 - 8 * lvl;
        const unsigned pref = bc[0];
        if (lvl > 0) {
            if (tid < 256) hist[tid] = 0;
            __syncthreads();
#pragma unroll 4
            for (int i = 0; i < HW / NT; i++) {
                unsigned k = keys[tid + i * NT];
                int d = ((k >> (shift + 8)) == pref) ? (int)((k >> shift) & 255u) : -1;
                agg_add(hist, d);
            }
            __syncthreads();
        }
        // Parallel suffix-sum of hist (Hillis-Steele, 8 steps)
        if (tid < 256) sa[tid] = hist[tid];
        __syncthreads();
        int* src = sa; int* dst = sb;
        for (int off = 1; off < 256; off <<= 1) {
            if (tid < 256) dst[tid] = src[tid] + ((tid + off < 256) ? src[tid + off] : 0);
            __syncthreads();
            int* t = src; src = dst; dst = t;
        }
        const int rem = (int)bc[1];
        __syncthreads();
        if (tid < 256) {
            int s = src[tid];
            int snext = (tid < 255) ? src[tid + 1] : 0;
            if (s >= rem && snext < rem) {        // exactly one thread matches
                bc[0] = (pref << 8) | (unsigned)tid;
                bc[1] = (unsigned)(rem - snext);
            }
        }
        __syncthreads();
    }

    // Final pass: sum of strictly-greater values; ties filled with T's value
    const unsigned T = bc[0];
    float lsum = 0.f; int lcnt = 0;
#pragma unroll 4
    for (int i = 0; i < HW / NT; i++) {
        unsigned k = keys[tid + i * NT];
        if (k > T) { lsum += key2f(k); lcnt++; }
    }
#pragma unroll
    for (int o = 16; o; o >>= 1) {
        lsum += __shfl_down_sync(0xffffffffu, lsum, o);
        lcnt += __shfl_down_sync(0xffffffffu, lcnt, o);
    }
    __syncthreads();
    float* fs = (float*)sa;
    int*   is = sb;
    if ((tid & 31) == 0) { fs[tid >> 5] = lsum; is[tid >> 5] = lcnt; }
    __syncthreads();
    if (tid == 0) {
        float s = 0.f; int c = 0;
        for (int w = 0; w < NT / 32; w++) { s += fs[w]; c += is[w]; }
        int r = TOPK - c;                      // number of tied values to include
        g_avg[row] = (s + key2f(T) * (float)r) / (float)TOPK;
    }
}

// ---------------------------------------------------------------------------
// Pass 1.5: tiny shared MLP per batch: sigmoid(mlp(avg)+mlp(max)) -> g_scale
// ---------------------------------------------------------------------------
__global__ void mlp_kernel(const float* __restrict__ w1, const float* __restrict__ b1,
                           const float* __restrict__ w2, const float* __restrict__ b2) {
    __shared__ float avg[CC], mx[CC], h[2 * HID];
    const int b = blockIdx.x, c = threadIdx.x;
    avg[c] = g_avg[b * CC + c];
    mx[c]  = g_maxv[b * CC + c];
    __syncthreads();
    if (c < 2 * HID) {
        int j = c & (HID - 1);
        const float* pool = (c < HID) ? avg : mx;
        float s = b1[j];
        for (int i = 0; i < CC; i++) s += pool[i] * w1[i * HID + j];
        h[c] = fmaxf(s, 0.f);
    }
    __syncthreads();
    float s = 2.f * b2[c];
#pragma unroll
    for (int j = 0; j < HID; j++) s += (h[j] + h[HID + j]) * w2[j * CC + c];
    g_scale[b * CC + c] = 1.f / (1.f + __expf(-s));
}

// ---------------------------------------------------------------------------
// Pass 2: y = x * scale[b, c]   (float4, one block per row)
// ---------------------------------------------------------------------------
__global__ __launch_bounds__(256) void scale_kernel(const float* __restrict__ x,
                                                    float* __restrict__ y) {
    const int row = blockIdx.x;
    const float s = g_scale[row];
    const float4* xi = (const float4*)(x + (size_t)row * HW);
    float4* yo = (float4*)(y + (size_t)row * HW);
    const int t = threadIdx.x;
#pragma unroll
    for (int i = 0; i < HW / (4 * 256); i++) {
        float4 v = xi[t + i * 256];
        v.x *= s; v.y *= s; v.z *= s; v.w *= s;
        yo[t + i * 256] = v;
    }
}

extern "C" void kernel_launch(void* const* d_in, const int* in_sizes, int n_in,
                              void* d_out, int out_size) {
    const float* x  = (const float*)d_in[0];
    const float* w1 = (const float*)d_in[1];
    const float* b1 = (const float*)d_in[2];
    const float* w2 = (const float*)d_in[3];
    const float* b2 = (const float*)d_in[4];
    float* y = (float*)d_out;

    cudaFuncSetAttribute(topk_stats, cudaFuncAttributeMaxDynamicSharedMemorySize, SMEM_BYTES);

    topk_stats<<<ROWS, NT, SMEM_BYTES>>>(x);
    mlp_kernel<<<BB, CC>>>(w1, b1, w2, b2);
    scale_kernel<<<ROWS, 256>>>(x, y);
}